// round 2
// baseline (speedup 1.0000x reference)
#include <cuda_runtime.h>

// Problem constants
#define NS   65536
#define KEXP 8
#define DIN  74
#define WID  64
#define DOUT 32
#define TILE 256
#define NT   256
#define MAXTILES (NS / TILE + KEXP)
#define NSCAT 256          // scatter/hist blocks

// weight staging sizes (floats)
#define W0SZ (DIN * WID)   // 4736
#define W1SZ (WID * WID)   // 4096
#define W2SZ (WID * DOUT)  // 2048
#define WALL (W0SZ + WID + W1SZ + WID + W2SZ + DOUT)  // 11040

// smem: Xs[74][256] (reused as layer-1 out) + Hs[64][256] + all weights + sids
#define SMEM_BYTES ((DIN * TILE + WID * TILE + WALL) * 4 + TILE * 4)

typedef unsigned long long u64;

// ---------------- device scratch ----------------
__device__ int g_hist[KEXP];           // zero-initialized at load; k_scan re-zeroes after use
__device__ int g_offs[KEXP + 1];
__device__ int g_cursor[KEXP];
__device__ int g_order[NS];

// ---------------- packed fp32x2 helpers (sm_103a) ----------------
__device__ __forceinline__ u64 pk2(float x, float y) {
    u64 r; asm("mov.b64 %0, {%1, %2};" : "=l"(r) : "f"(x), "f"(y)); return r;
}
__device__ __forceinline__ void upk2(u64 p, float& x, float& y) {
    asm("mov.b64 {%0, %1}, %2;" : "=f"(x), "=f"(y) : "l"(p));
}
__device__ __forceinline__ void fma2(u64& c, u64 a, u64 b) {
    asm("fma.rn.f32x2 %0, %1, %2, %0;" : "+l"(c) : "l"(a), "l"(b));
}

// ---------------- bucketing ----------------
__global__ void k_hist(const int* __restrict__ idxs) {
    __shared__ int sh[KEXP];
    if (threadIdx.x < KEXP) sh[threadIdx.x] = 0;
    __syncthreads();
    atomicAdd(&sh[idxs[blockIdx.x * NT + threadIdx.x]], 1);
    __syncthreads();
    if (threadIdx.x < KEXP) atomicAdd(&g_hist[threadIdx.x], sh[threadIdx.x]);
}

__global__ void k_scan() {
    int acc = 0;
    for (int e = 0; e < KEXP; e++) {
        g_offs[e] = acc; g_cursor[e] = acc;
        acc += g_hist[e];
        g_hist[e] = 0;                 // reset for next graph replay
    }
    g_offs[KEXP] = acc;
}

__global__ void k_scatter(const int* __restrict__ idxs) {
    __shared__ int s_loc[KEXP];
    __shared__ int s_base[KEXP];
    if (threadIdx.x < KEXP) s_loc[threadIdx.x] = 0;
    __syncthreads();
    int i = blockIdx.x * NT + threadIdx.x;
    int e = idxs[i];
    int r = atomicAdd(&s_loc[e], 1);
    __syncthreads();
    if (threadIdx.x < KEXP)
        s_base[threadIdx.x] = atomicAdd(&g_cursor[threadIdx.x], s_loc[threadIdx.x]);
    __syncthreads();
    g_order[s_base[e] + r] = i;
}

// ---------------- cooperative weight copy (no internal sync) ----------------
__device__ __forceinline__ void copy_w(float* __restrict__ dst, const float* __restrict__ w,
                                       int nw4, const float* __restrict__ bias, int nb4, int tid) {
    float4* d4 = (float4*)dst;
    const float4* s4 = (const float4*)w;
    const float4* b4 = (const float4*)bias;
    for (int j = tid; j < nw4 + nb4; j += NT)
        d4[j] = (j < nw4) ? s4[j] : b4[j - nw4];
}

// ---------------- GEMM (pair-over-samples): [256 x KD] @ [KD x 64] + bias, relu ----------------
// A k-major [KD][256]; W [KD][64]; O [64][256]. Thread: 8 samples (4 pairs) x 8 cols.
template <int KD>
__device__ __forceinline__ void gemm_relu(const float* __restrict__ A,
                                          const float* __restrict__ W,
                                          const float* __restrict__ bias,
                                          float* __restrict__ O,
                                          int lane, int cg) {
    const int c0 = cg * 8;
    const int s0 = lane * 8;
    u64 acc[4][8];
#pragma unroll
    for (int j = 0; j < 8; j++) {
        float bv = bias[c0 + j];
        u64 b = pk2(bv, bv);
#pragma unroll
        for (int p = 0; p < 4; p++) acc[p][j] = b;
    }
#pragma unroll 2
    for (int k = 0; k < KD; k++) {
        u64 a[4];
#pragma unroll
        for (int p = 0; p < 4; p++)
            a[p] = *(const u64*)&A[k * TILE + s0 + 2 * p];   // direct LDS.64, no packing
        float4 w0 = *(const float4*)&W[k * WID + c0];         // warp-broadcast
        float4 w1 = *(const float4*)&W[k * WID + c0 + 4];
        u64 b[8] = { pk2(w0.x, w0.x), pk2(w0.y, w0.y), pk2(w0.z, w0.z), pk2(w0.w, w0.w),
                     pk2(w1.x, w1.x), pk2(w1.y, w1.y), pk2(w1.z, w1.z), pk2(w1.w, w1.w) };
#pragma unroll
        for (int p = 0; p < 4; p++)
#pragma unroll
            for (int j = 0; j < 8; j++)
                fma2(acc[p][j], a[p], b[j]);
    }
#pragma unroll
    for (int j = 0; j < 8; j++) {
#pragma unroll
        for (int p = 0; p < 4; p++) {
            float x0, x1; upk2(acc[p][j], x0, x1);
            float2 v = make_float2(fmaxf(x0, 0.0f), fmaxf(x1, 0.0f));
            *(float2*)&O[(c0 + j) * TILE + s0 + 2 * p] = v;
        }
    }
}

// ---------------- final layer: [256 x 64] @ [64 x 32] + bias -> global scatter ----------------
__device__ __forceinline__ void gemm_out(const float* __restrict__ A, const float* __restrict__ W,
                                         const float* __restrict__ bias, float* __restrict__ out,
                                         const int* __restrict__ sids, int cnt, int lane, int cg) {
    const int c0 = cg * 4;
    const int s0 = lane * 8;
    u64 acc[4][4];
#pragma unroll
    for (int j = 0; j < 4; j++) {
        float bv = bias[c0 + j];
        u64 b = pk2(bv, bv);
#pragma unroll
        for (int p = 0; p < 4; p++) acc[p][j] = b;
    }
#pragma unroll 2
    for (int k = 0; k < WID; k++) {
        u64 a[4];
#pragma unroll
        for (int p = 0; p < 4; p++)
            a[p] = *(const u64*)&A[k * TILE + s0 + 2 * p];
        float4 w = *(const float4*)&W[k * DOUT + c0];
        u64 b[4] = { pk2(w.x, w.x), pk2(w.y, w.y), pk2(w.z, w.z), pk2(w.w, w.w) };
#pragma unroll
        for (int p = 0; p < 4; p++)
#pragma unroll
            for (int j = 0; j < 4; j++)
                fma2(acc[p][j], a[p], b[j]);
    }
#pragma unroll
    for (int p = 0; p < 4; p++) {
        float lo[4], hi[4];
#pragma unroll
        for (int j = 0; j < 4; j++) upk2(acc[p][j], lo[j], hi[j]);
        int r0 = s0 + 2 * p;
        if (r0 < cnt)
            *(float4*)&out[(size_t)sids[r0] * DOUT + c0] = make_float4(lo[0], lo[1], lo[2], lo[3]);
        if (r0 + 1 < cnt)
            *(float4*)&out[(size_t)sids[r0 + 1] * DOUT + c0] = make_float4(hi[0], hi[1], hi[2], hi[3]);
    }
}

// ---------------- fused MLP kernel ----------------
__global__ void __launch_bounds__(NT) k_mlp(
    const float* __restrict__ positions, const float* __restrict__ viewdirs,
    const float* __restrict__ features,
    const float* __restrict__ W0, const float* __restrict__ b0,
    const float* __restrict__ W1, const float* __restrict__ b1,
    const float* __restrict__ W2, const float* __restrict__ b2,
    float* __restrict__ out) {
    extern __shared__ float sm[];
    float* Xs = sm;                       // [74][256], reused as layer-1 output [64][256]
    float* Hs = sm + DIN * TILE;          // [64][256]
    float* Wa = Hs + WID * TILE;          // all weights: W0|b0|W1|b1|W2|b2
    int* sids = (int*)(Wa + WALL);
    int tid = threadIdx.x;

    float* Wb0 = Wa;
    float* Bb0 = Wb0 + W0SZ;
    float* Wb1 = Bb0 + WID;
    float* Bb1 = Wb1 + W1SZ;
    float* Wb2 = Bb1 + WID;
    float* Bb2 = Wb2 + W2SZ;

    // blockIdx -> (expert, local tile)
    int e = -1, lt = 0;
    {
        int b = blockIdx.x, acc = 0;
#pragma unroll
        for (int i = 0; i < KEXP; i++) {
            int tiles = (g_offs[i + 1] - g_offs[i] + TILE - 1) / TILE;
            if (e < 0 && b < acc + tiles) { e = i; lt = b - acc; }
            acc += tiles;
        }
    }
    if (e < 0) return;
    int base = g_offs[e] + lt * TILE;
    int cnt = min(TILE, g_offs[e + 1] - base);

    int n = g_order[base + min(tid, cnt - 1)];   // pad partial tiles with a valid row
    sids[tid] = n;

    // ---- stage ALL weights once (overlaps with gather/encode below via ILP) ----
    copy_w(Wb0, W0 + e * W0SZ, W0SZ / 4, b0 + e * WID, WID / 4, tid);
    copy_w(Wb1, W1 + e * W1SZ, W1SZ / 4, b1 + e * WID, WID / 4, tid);
    copy_w(Wb2, W2 + e * W2SZ, W2SZ / 4, b2 + e * DOUT, DOUT / 4, tid);

    // ---- gather + encode row `tid` into Xs (k-major) ----
    const float4* f4 = (const float4*)(features + (size_t)n * 32);
#pragma unroll
    for (int i = 0; i < 8; i++) {
        float4 f = f4[i];
        Xs[(i * 4 + 0) * TILE + tid] = f.x;
        Xs[(i * 4 + 1) * TILE + tid] = f.y;
        Xs[(i * 4 + 2) * TILE + tid] = f.z;
        Xs[(i * 4 + 3) * TILE + tid] = f.w;
    }
    {
        float p0 = positions[n * 3], p1 = positions[n * 3 + 1], p2 = positions[n * 3 + 2];
        Xs[32 * TILE + tid] = p0; Xs[33 * TILE + tid] = p1; Xs[34 * TILE + tid] = p2;
#pragma unroll
        for (int s = 0; s < 2; s++) {
            float sc = (float)(1 << s);
            float v0 = p0 * sc, v1 = p1 * sc, v2 = p2 * sc;
            Xs[(35 + s * 3) * TILE + tid] = __sinf(v0);
            Xs[(36 + s * 3) * TILE + tid] = __sinf(v1);
            Xs[(37 + s * 3) * TILE + tid] = __sinf(v2);
            Xs[(41 + s * 3) * TILE + tid] = __cosf(v0);
            Xs[(42 + s * 3) * TILE + tid] = __cosf(v1);
            Xs[(43 + s * 3) * TILE + tid] = __cosf(v2);
        }
        float q0 = viewdirs[n * 3], q1 = viewdirs[n * 3 + 1], q2 = viewdirs[n * 3 + 2];
        Xs[47 * TILE + tid] = q0; Xs[48 * TILE + tid] = q1; Xs[49 * TILE + tid] = q2;
#pragma unroll
        for (int s = 0; s < 4; s++) {
            float sc = (float)(1 << s);
            float v0 = q0 * sc, v1 = q1 * sc, v2 = q2 * sc;
            Xs[(50 + s * 3) * TILE + tid] = __sinf(v0);
            Xs[(51 + s * 3) * TILE + tid] = __sinf(v1);
            Xs[(52 + s * 3) * TILE + tid] = __sinf(v2);
            Xs[(62 + s * 3) * TILE + tid] = __cosf(v0);
            Xs[(63 + s * 3) * TILE + tid] = __cosf(v1);
            Xs[(64 + s * 3) * TILE + tid] = __cosf(v2);
        }
    }
    __syncthreads();

    int lane = tid & 31, cg = tid >> 5;
    gemm_relu<DIN>(Xs, Wb0, Bb0, Hs, lane, cg);
    __syncthreads();
    gemm_relu<WID>(Hs, Wb1, Bb1, Xs, lane, cg);
    __syncthreads();
    gemm_out(Xs, Wb2, Bb2, out, sids, cnt, lane, cg);
}

// ---------------- launch ----------------
extern "C" void kernel_launch(void* const* d_in, const int* in_sizes, int n_in,
                              void* d_out, int out_size) {
    (void)in_sizes; (void)n_in; (void)out_size;
    const int*   idxs      = (const int*)d_in[0];
    const float* positions = (const float*)d_in[1];
    const float* viewdirs  = (const float*)d_in[2];
    const float* features  = (const float*)d_in[3];
    const float* W0 = (const float*)d_in[4];
    const float* b0 = (const float*)d_in[5];
    const float* W1 = (const float*)d_in[6];
    const float* b1 = (const float*)d_in[7];
    const float* W2 = (const float*)d_in[8];
    const float* b2 = (const float*)d_in[9];
    float* out = (float*)d_out;

    cudaFuncSetAttribute(k_mlp, cudaFuncAttributeMaxDynamicSharedMemorySize, SMEM_BYTES);

    k_hist<<<NSCAT, NT>>>(idxs);
    k_scan<<<1, 1>>>();
    k_scatter<<<NSCAT, NT>>>(idxs);
    k_mlp<<<MAXTILES, NT, SMEM_BYTES>>>(positions, viewdirs, features,
                                        W0, b0, W1, b1, W2, b2, out);
}